// round 7
// baseline (speedup 1.0000x reference)
#include <cuda_runtime.h>

#define Bc  4
#define LXc 384
#define LYc 384
#define Hc  256
#define Fc  512

typedef unsigned long long ull;

// scratch (allocation-free rule: __device__ globals)
__device__ float g_Xp[Bc * LXc * Hc];   // x @ Wm^T
__device__ float g_Yp[Bc * LYc * Hc];   // y @ Wm^T
__device__ float g_S [Bc * LYc * LXc];  // scores -> softmax'd in place

__device__ __forceinline__ float tanh_fast(float x) {
    float r; asm("tanh.approx.f32 %0, %1;" : "=f"(r) : "f"(x)); return r;
}
__device__ __forceinline__ float ex2_fast(float x) {
    float r; asm("ex2.approx.f32 %0, %1;" : "=f"(r) : "f"(x)); return r;
}
__device__ __forceinline__ float2 unpack2(ull v) {
    float lo, hi; asm("mov.b64 {%0, %1}, %2;" : "=f"(lo), "=f"(hi) : "l"(v));
    return make_float2(lo, hi);
}
__device__ __forceinline__ ull fma2(ull a, ull b, ull c) {
    ull r; asm("fma.rn.f32x2 %0, %1, %2, %3;" : "=l"(r) : "l"(a), "l"(b), "l"(c));
    return r;
}

// ---------------------------------------------------------------------------
// Kernel 1: Out[r,h] = sum_f In[r,f] * W[h,f]   (NT GEMM, both K-major)
// M=1536, N=256, K=512.  32x64 tile, 256 threads (8 warps), 2x4 micro-tile,
// BK=16 double-buffered, FFMA2 with pre-duplicated A operand in smem.
// grid (48, 4, 2) = 384 blocks -> 2.6 blocks/SM = 20.8 warps/SM.
// ---------------------------------------------------------------------------
__global__ __launch_bounds__(256) void proj_kernel(
    const float* __restrict__ xin, const float* __restrict__ yin,
    const float* __restrict__ W)
{
    const float* In  = blockIdx.z ? yin  : xin;
    float*       Out = blockIdx.z ? g_Yp : g_Xp;

    __shared__ float As[2][16][68];   // [k][m dup: 2*32=64 used] 272B stride
    __shared__ float Bs[2][16][68];   // [k][n(64)]

    const int tid = threadIdx.x;
    const int r0  = blockIdx.x * 32;
    const int h0  = blockIdx.y * 64;

    const int lrA = tid >> 3;           // 0..31 (m row for A load)
    const int kA  = (tid & 7) * 2;      // k sub for A load (2 floats)
    const int lrB = tid >> 2;           // 0..63 (n row for B load)
    const int kB  = (tid & 3) * 4;      // k sub for B load (4 floats)

    const int tx = tid & 15;            // n micro-col (4 cols)
    const int ty = tid >> 4;            // m micro-row pair (0..15 -> 2 rows)

    const float* pA = &In[(r0 + lrA) * Fc + kA];
    const float* pB = &W [(h0 + lrB) * Fc + kB];

    ull acc[2][2] = {};

    // prologue: chunk 0 -> buf 0
    {
        float2 av = *(const float2*)pA;
        float4 bv = *(const float4*)pB;
        *(float2*)&As[0][kA + 0][lrA * 2] = make_float2(av.x, av.x);
        *(float2*)&As[0][kA + 1][lrA * 2] = make_float2(av.y, av.y);
        Bs[0][kB + 0][lrB] = bv.x; Bs[0][kB + 1][lrB] = bv.y;
        Bs[0][kB + 2][lrB] = bv.z; Bs[0][kB + 3][lrB] = bv.w;
    }
    __syncthreads();

    int buf = 0;
    for (int k0 = 16; k0 <= Fc; k0 += 16) {
        float2 av; float4 bv;
        if (k0 < Fc) {
            av = *(const float2*)(pA + k0);
            bv = *(const float4*)(pB + k0);
        }
        #pragma unroll
        for (int kk = 0; kk < 16; kk++) {
            ull ax  = *(const ull*)&As[buf][kk][ty * 4];
            ull ay  = *(const ull*)&As[buf][kk][ty * 4 + 2];
            ull b01 = *(const ull*)&Bs[buf][kk][tx * 4];
            ull b23 = *(const ull*)&Bs[buf][kk][tx * 4 + 2];
            acc[0][0] = fma2(ax, b01, acc[0][0]);
            acc[0][1] = fma2(ax, b23, acc[0][1]);
            acc[1][0] = fma2(ay, b01, acc[1][0]);
            acc[1][1] = fma2(ay, b23, acc[1][1]);
        }
        if (k0 < Fc) {
            int nb = buf ^ 1;
            *(float2*)&As[nb][kA + 0][lrA * 2] = make_float2(av.x, av.x);
            *(float2*)&As[nb][kA + 1][lrA * 2] = make_float2(av.y, av.y);
            Bs[nb][kB + 0][lrB] = bv.x; Bs[nb][kB + 1][lrB] = bv.y;
            Bs[nb][kB + 2][lrB] = bv.z; Bs[nb][kB + 3][lrB] = bv.w;
            __syncthreads();
            buf = nb;
        }
    }

    #pragma unroll
    for (int i = 0; i < 2; i++) {
        float2 p0 = unpack2(acc[i][0]);
        float2 p1 = unpack2(acc[i][1]);
        *(float4*)&Out[(r0 + ty * 2 + i) * Hc + h0 + tx * 4] =
            make_float4(p0.x, p0.y, p1.x, p1.y);
    }
}

// ---------------------------------------------------------------------------
// Kernel 2: GEMM-shaped tanh-score (MUFU-bound, at its floor — unchanged).
// S[b,y,l] = sum_h vm[h] * tanh(Xp[b,l,h] - Yp[b,y,h])
// ---------------------------------------------------------------------------
__global__ __launch_bounds__(256) void score_tile_kernel(const float* __restrict__ vm)
{
    const int b  = blockIdx.z;
    const int y0 = blockIdx.y * 64;
    const int l0 = blockIdx.x * 64;

    __shared__ float Ys[16][68];
    __shared__ float Xs[16][68];
    __shared__ float Vs[Hc];

    const int tid = threadIdx.x;
    for (int i = tid; i < Hc; i += 256) Vs[i] = vm[i];

    const int lrow = tid >> 2;
    const int f4   = (tid & 3) * 4;
    const int tx   = tid & 15;
    const int ty   = tid >> 4;

    const float* Yb = g_Yp + (b * LYc + y0) * Hc;
    const float* Xb = g_Xp + (b * LXc + l0) * Hc;

    float acc[4][4] = {};

    for (int k0 = 0; k0 < Hc; k0 += 16) {
        float4 av = *(const float4*)&Yb[lrow * Hc + k0 + f4];
        float4 bv = *(const float4*)&Xb[lrow * Hc + k0 + f4];
        __syncthreads();
        Ys[f4 + 0][lrow] = av.x; Ys[f4 + 1][lrow] = av.y;
        Ys[f4 + 2][lrow] = av.z; Ys[f4 + 3][lrow] = av.w;
        Xs[f4 + 0][lrow] = bv.x; Xs[f4 + 1][lrow] = bv.y;
        Xs[f4 + 2][lrow] = bv.z; Xs[f4 + 3][lrow] = bv.w;
        __syncthreads();

        #pragma unroll
        for (int kk = 0; kk < 16; kk++) {
            const float v = Vs[k0 + kk];
            float4 yv = *(const float4*)&Ys[kk][ty * 4];
            float4 xv = *(const float4*)&Xs[kk][tx * 4];
            float t00 = tanh_fast(xv.x - yv.x);
            float t01 = tanh_fast(xv.y - yv.x);
            float t02 = tanh_fast(xv.z - yv.x);
            float t03 = tanh_fast(xv.w - yv.x);
            float t10 = tanh_fast(xv.x - yv.y);
            float t11 = tanh_fast(xv.y - yv.y);
            float t12 = tanh_fast(xv.z - yv.y);
            float t13 = tanh_fast(xv.w - yv.y);
            float t20 = tanh_fast(xv.x - yv.z);
            float t21 = tanh_fast(xv.y - yv.z);
            float t22 = tanh_fast(xv.z - yv.z);
            float t23 = tanh_fast(xv.w - yv.z);
            float t30 = tanh_fast(xv.x - yv.w);
            float t31 = tanh_fast(xv.y - yv.w);
            float t32 = tanh_fast(xv.z - yv.w);
            float t33 = tanh_fast(xv.w - yv.w);
            acc[0][0] = fmaf(v, t00, acc[0][0]);
            acc[0][1] = fmaf(v, t01, acc[0][1]);
            acc[0][2] = fmaf(v, t02, acc[0][2]);
            acc[0][3] = fmaf(v, t03, acc[0][3]);
            acc[1][0] = fmaf(v, t10, acc[1][0]);
            acc[1][1] = fmaf(v, t11, acc[1][1]);
            acc[1][2] = fmaf(v, t12, acc[1][2]);
            acc[1][3] = fmaf(v, t13, acc[1][3]);
            acc[2][0] = fmaf(v, t20, acc[2][0]);
            acc[2][1] = fmaf(v, t21, acc[2][1]);
            acc[2][2] = fmaf(v, t22, acc[2][2]);
            acc[2][3] = fmaf(v, t23, acc[2][3]);
            acc[3][0] = fmaf(v, t30, acc[3][0]);
            acc[3][1] = fmaf(v, t31, acc[3][1]);
            acc[3][2] = fmaf(v, t32, acc[3][2]);
            acc[3][3] = fmaf(v, t33, acc[3][3]);
        }
    }

    float* Sb = g_S + (b * LYc + y0) * LXc + l0;
    #pragma unroll
    for (int i = 0; i < 4; i++) {
        float4 st = make_float4(acc[i][0], acc[i][1], acc[i][2], acc[i][3]);
        *(float4*)&Sb[(ty * 4 + i) * LXc + tx * 4] = st;
    }
}

// ---------------------------------------------------------------------------
// Kernel 3a: softmax over l, in place on g_S. Warp per row.
// ---------------------------------------------------------------------------
__global__ __launch_bounds__(256) void softmax_kernel()
{
    const int b    = blockIdx.y;
    const int y    = blockIdx.x * 8 + (threadIdx.x >> 5);
    const int lane = threadIdx.x & 31;

    float* Srow = g_S + (b * LYc + y) * LXc;
    float v[12];
    float mx = -1e30f;
    #pragma unroll
    for (int j = 0; j < 12; j++) {
        v[j] = Srow[lane + 32 * j];
        mx = fmaxf(mx, v[j]);
    }
    #pragma unroll
    for (int o = 16; o; o >>= 1)
        mx = fmaxf(mx, __shfl_xor_sync(0xffffffffu, mx, o));
    float sum = 0.f;
    #pragma unroll
    for (int j = 0; j < 12; j++) {
        v[j] = ex2_fast((v[j] - mx) * 1.4426950408889634f);
        sum += v[j];
    }
    #pragma unroll
    for (int o = 16; o; o >>= 1)
        sum += __shfl_xor_sync(0xffffffffu, sum, o);
    float inv = 1.0f / sum;
    #pragma unroll
    for (int j = 0; j < 12; j++)
        Srow[lane + 32 * j] = v[j] * inv;
}

// ---------------------------------------------------------------------------
// Kernel 3b: qtm[b,y,f] = sum_l A[b,y,l] * x[b,l,f]
// Per-batch GEMM M=384(y), N=512(f), K=384(l).  32x64 tile, 256 threads,
// 2x4 micro-tile, BK=16 double-buffered, FFMA2, dup-A smem.
// grid (8, 12, 4) = 384 blocks.
// ---------------------------------------------------------------------------
__global__ __launch_bounds__(256) void outgemm_kernel(
    const float* __restrict__ x, float* __restrict__ out)
{
    const int b  = blockIdx.z;
    const int f0 = blockIdx.x * 64;
    const int y0 = blockIdx.y * 32;

    __shared__ float As[2][16][68];   // [k(l)][y dup: 64 used]
    __shared__ float Xs[2][16][68];   // [k(l)][f(64)]

    const int tid = threadIdx.x;

    const int lrA = tid >> 3;           // 0..31 (y row for A load)
    const int kA  = (tid & 7) * 2;      // l sub for A load (2 floats)
    const int lX  = tid >> 4;           // 0..15 (l row for X load)
    const int fX  = (tid & 15) * 4;     // f sub for X load (4 floats)

    const int tx = tid & 15;            // f micro-col
    const int ty = tid >> 4;            // y micro-row pair

    const float* pA = g_S + (b * LYc + y0 + lrA) * LXc + kA;
    const float* pX = x + b * LXc * Fc + lX * Fc + f0 + fX;

    ull acc[2][2] = {};

    {
        float2 av = *(const float2*)pA;
        float4 xv = *(const float4*)pX;
        *(float2*)&As[0][kA + 0][lrA * 2] = make_float2(av.x, av.x);
        *(float2*)&As[0][kA + 1][lrA * 2] = make_float2(av.y, av.y);
        *(float4*)&Xs[0][lX][fX] = xv;
    }
    __syncthreads();

    int buf = 0;
    for (int k0 = 16; k0 <= LXc; k0 += 16) {
        float2 av; float4 xv;
        if (k0 < LXc) {
            av = *(const float2*)(pA + k0);
            xv = *(const float4*)(pX + k0 * Fc);
        }
        #pragma unroll
        for (int kk = 0; kk < 16; kk++) {
            ull ax  = *(const ull*)&As[buf][kk][ty * 4];
            ull ay  = *(const ull*)&As[buf][kk][ty * 4 + 2];
            ull b01 = *(const ull*)&Xs[buf][kk][tx * 4];
            ull b23 = *(const ull*)&Xs[buf][kk][tx * 4 + 2];
            acc[0][0] = fma2(ax, b01, acc[0][0]);
            acc[0][1] = fma2(ax, b23, acc[0][1]);
            acc[1][0] = fma2(ay, b01, acc[1][0]);
            acc[1][1] = fma2(ay, b23, acc[1][1]);
        }
        if (k0 < LXc) {
            int nb = buf ^ 1;
            *(float2*)&As[nb][kA + 0][lrA * 2] = make_float2(av.x, av.x);
            *(float2*)&As[nb][kA + 1][lrA * 2] = make_float2(av.y, av.y);
            *(float4*)&Xs[nb][lX][fX] = xv;
            __syncthreads();
            buf = nb;
        }
    }

    #pragma unroll
    for (int i = 0; i < 2; i++) {
        float2 p0 = unpack2(acc[i][0]);
        float2 p1 = unpack2(acc[i][1]);
        *(float4*)&out[(b * LYc + y0 + ty * 2 + i) * Fc + f0 + tx * 4] =
            make_float4(p0.x, p0.y, p1.x, p1.y);
    }
}

// ---------------------------------------------------------------------------
extern "C" void kernel_launch(void* const* d_in, const int* in_sizes, int n_in,
                              void* d_out, int out_size)
{
    const float* x  = (const float*)d_in[0];
    const float* y  = (const float*)d_in[1];
    const float* Wm = (const float*)d_in[2];
    const float* vm = (const float*)d_in[3];
    float* out = (float*)d_out;

    proj_kernel      <<<dim3(LXc * Bc / 32, Hc / 64, 2), 256>>>(x, y, Wm);
    score_tile_kernel<<<dim3(LXc / 64, LYc / 64, Bc), 256>>>(vm);
    softmax_kernel   <<<dim3(LYc / 8, Bc), 256>>>();
    outgemm_kernel   <<<dim3(Fc / 64, LYc / 32, Bc), 256>>>(x, out);
}